// round 1
// baseline (speedup 1.0000x reference)
#include <cuda_runtime.h>

// CAMField: out = MLP(xy) with per-layer bilinear FiLM modulation from 16x16 grids.
// Key perf decisions:
//  - Fold ln_w/ln_b into gamma/beta grids once per launch (exact: interp is linear).
//  - Grid table in shared memory, cell stride 28 floats (112B) so random 16B-aligned
//    LDS.128 starts hit all 8 bank groups.
//  - ZERO MUFU: polynomial exp2 + bit-scale for silu, Newton reciprocal and rsqrt.

#define GR 16
#define NCELL 256
#define CSTR 28   // floats per cell in smem (24 data + 4 pad)

__device__ float g_grid[NCELL * 24];

// ---------------- prep: fold layernorm affine into grids ----------------
// A[l][cell][c] = gamma[l,c,cell] * ln_w[l,c]
// B[l][cell][c] = beta[l,c,cell] + gamma[l,c,cell] * ln_b[l,c]
__global__ void prep_kernel(const float* __restrict__ gamma,
                            const float* __restrict__ beta,
                            const float* __restrict__ ln_w,
                            const float* __restrict__ ln_b) {
    int idx = blockIdx.x * blockDim.x + threadIdx.x;
    if (idx >= NCELL * 12) return;
    int cell = idx / 12;
    int j = idx % 12;
    int l = j / 6, c = j % 6;
    int gidx = (l * 6 + c) * NCELL + cell;   // [L][C][16][16], cell = y*16+x
    float ga = gamma[gidx], be = beta[gidx];
    float lw = ln_w[l * 6 + c], lb = ln_b[l * 6 + c];
    g_grid[cell * 24 + l * 12 + c]     = ga * lw;
    g_grid[cell * 24 + l * 12 + 6 + c] = fmaf(ga, lb, be);
}

// ---------------- MUFU-free math ----------------

// reciprocal of d in [1,2]: linear minimax seed (max rel err 1/17) + 3 Newton
__device__ __forceinline__ float fast_rcp12(float d) {
    float r = fmaf(d, -8.0f / 17.0f, 24.0f / 17.0f);
    r = r * fmaf(-d, r, 2.0f);
    r = r * fmaf(-d, r, 2.0f);
    r = r * fmaf(-d, r, 2.0f);
    return r;
}

__device__ __forceinline__ float fast_rsqrt(float v) {
    float r = __int_as_float(0x5f3759df - (__float_as_int(v) >> 1));
    float hv = 0.5f * v;
    float rr;
    rr = r * r; r = r * fmaf(-hv, rr, 1.5f);
    rr = r * r; r = r * fmaf(-hv, rr, 1.5f);
    rr = r * r; r = r * fmaf(-hv, rr, 1.5f);
    return r;
}

// silu(x) = x * sigmoid(x), no MUFU.
// Compute t = 2^(-|x|*log2e) via round-to-int bit trick + degree-5 poly on [-0.5,0.5],
// s = t/(1+t) = sigmoid(-|x|), then reflect for x>0.
__device__ __forceinline__ float fast_silu(float x) {
    const float L2E = 1.4426950408889634f;
    float y = fmaxf(-fabsf(x) * L2E, -60.0f);
    float fm = y + 12582912.0f;                 // 1.5*2^23: RN rounds y to integer
    int   n  = __float_as_int(fm);              // low bits hold round(y) (mod 2^9 ok)
    float f  = y - (fm - 12582912.0f);          // f in [-0.5, 0.5]
    // 2^f = e^(f ln2), Taylor deg 5 (rel err < 3e-6 on this range)
    float p;
    p = fmaf(f, 1.3333558e-3f, 9.6181291e-3f);
    p = fmaf(f, p, 5.5504109e-2f);
    p = fmaf(f, p, 2.4022651e-1f);
    p = fmaf(f, p, 6.9314718e-1f);
    p = fmaf(f, p, 1.0f);
    float t = __int_as_float(__float_as_int(p) + (int)((unsigned)n << 23)); // 2^y
    float d = 1.0f + t;                          // in [1,2]
    float s = t * fast_rcp12(d);                 // sigmoid(-|x|) in (0, 0.5]
    float m = x * s;
    return (x > 0.0f) ? (x - m) : m;             // x>0: x*(1-s); x<=0: x*s
}

// ---------------- interpolation helper ----------------
__device__ __forceinline__ void interp12(const float4* __restrict__ c00,
                                         const float4* __restrict__ c01,
                                         const float4* __restrict__ c10,
                                         const float4* __restrict__ c11,
                                         int off,
                                         float w00, float w01, float w10, float w11,
                                         float* v) {
#pragma unroll
    for (int q = 0; q < 3; q++) {
        float4 a = c00[off + q];
        float4 b = c01[off + q];
        float4 c = c10[off + q];
        float4 d = c11[off + q];
        v[4 * q + 0] = fmaf(w00, a.x, fmaf(w01, b.x, fmaf(w10, c.x, w11 * d.x)));
        v[4 * q + 1] = fmaf(w00, a.y, fmaf(w01, b.y, fmaf(w10, c.y, w11 * d.y)));
        v[4 * q + 2] = fmaf(w00, a.z, fmaf(w01, b.z, fmaf(w10, c.z, w11 * d.z)));
        v[4 * q + 3] = fmaf(w00, a.w, fmaf(w01, b.w, fmaf(w10, c.w, w11 * d.w)));
    }
}

// ---------------- main kernel ----------------
__global__ __launch_bounds__(128)
void camfield_kernel(const float2* __restrict__ xy,
                     const float* __restrict__ w_in, const float* __restrict__ b_in,
                     const float* __restrict__ w_h,  const float* __restrict__ b_h,
                     const float* __restrict__ w_out,const float* __restrict__ b_out,
                     float* __restrict__ out, int n) {
    __shared__ float sg[NCELL * CSTR];   // 28 KB
    for (int i = threadIdx.x; i < NCELL * 24; i += blockDim.x)
        sg[(i / 24) * CSTR + (i % 24)] = g_grid[i];

    // small weights -> registers (uniform per thread)
    float wi[12], bi[6], wh[36], bh[6], wo[18], bo[3];
#pragma unroll
    for (int k = 0; k < 12; k++) wi[k] = __ldg(w_in + k);
#pragma unroll
    for (int k = 0; k < 6; k++)  bi[k] = __ldg(b_in + k);
#pragma unroll
    for (int k = 0; k < 36; k++) wh[k] = __ldg(w_h + k);
#pragma unroll
    for (int k = 0; k < 6; k++)  bh[k] = __ldg(b_h + k);
#pragma unroll
    for (int k = 0; k < 18; k++) wo[k] = __ldg(w_out + k);
#pragma unroll
    for (int k = 0; k < 3; k++)  bo[k] = __ldg(b_out + k);
    __syncthreads();

    const int stride = gridDim.x * blockDim.x;
    for (int i = blockIdx.x * blockDim.x + threadIdx.x; i < n; i += stride) {
        float2 p = xy[i];

        // grid-sample coords (align_corners=True, border padding)
        float fx = fminf(fmaxf(fmaf(p.x, 7.5f, 7.5f), 0.0f), 15.0f);
        float fy = fminf(fmaxf(fmaf(p.y, 7.5f, 7.5f), 0.0f), 15.0f);
        float x0f = floorf(fx), y0f = floorf(fy);
        float wx = fx - x0f, wy = fy - y0f;
        int x0 = (int)x0f, y0 = (int)y0f;
        int x1 = min(x0 + 1, GR - 1), y1 = min(y0 + 1, GR - 1);
        int r0 = y0 << 4, r1 = y1 << 4;
        const float4* c00 = (const float4*)&sg[(r0 + x0) * CSTR];
        const float4* c01 = (const float4*)&sg[(r0 + x1) * CSTR];
        const float4* c10 = (const float4*)&sg[(r1 + x0) * CSTR];
        const float4* c11 = (const float4*)&sg[(r1 + x1) * CSTR];
        float w11 = wx * wy;
        float w01 = wx - w11;
        float w10 = wy - w11;
        float w00 = 1.0f - wx - wy + w11;

        // input layer: h = silu(xy @ w_in^T + b_in)
        float h[6];
#pragma unroll
        for (int c = 0; c < 6; c++)
            h[c] = fast_silu(fmaf(wi[2 * c], p.x, fmaf(wi[2 * c + 1], p.y, bi[c])));

        // ---- layer 0 modulation ----
        {
            float v[12];
            interp12(c00, c01, c10, c11, 0, w00, w01, w10, w11, v);
            float mu = (((h[0] + h[1]) + (h[2] + h[3])) + (h[4] + h[5])) * (1.0f / 6.0f);
            float cen[6], ss = 0.0f;
#pragma unroll
            for (int c = 0; c < 6; c++) { cen[c] = h[c] - mu; ss = fmaf(cen[c], cen[c], ss); }
            float rs = fast_rsqrt(fmaf(ss, 1.0f / 6.0f, 1e-5f));
#pragma unroll
            for (int c = 0; c < 6; c++) h[c] = fmaf(v[c], cen[c] * rs, v[6 + c]);
        }

        // hidden layer: h = silu(h @ w_h^T + b_h)
        {
            float nh[6];
#pragma unroll
            for (int c = 0; c < 6; c++) {
                float acc = bh[c];
#pragma unroll
                for (int k = 0; k < 6; k++) acc = fmaf(wh[c * 6 + k], h[k], acc);
                nh[c] = fast_silu(acc);
            }
#pragma unroll
            for (int c = 0; c < 6; c++) h[c] = nh[c];
        }

        // ---- layer 1 modulation ----
        {
            float v[12];
            interp12(c00, c01, c10, c11, 3, w00, w01, w10, w11, v);
            float mu = (((h[0] + h[1]) + (h[2] + h[3])) + (h[4] + h[5])) * (1.0f / 6.0f);
            float cen[6], ss = 0.0f;
#pragma unroll
            for (int c = 0; c < 6; c++) { cen[c] = h[c] - mu; ss = fmaf(cen[c], cen[c], ss); }
            float rs = fast_rsqrt(fmaf(ss, 1.0f / 6.0f, 1e-5f));
#pragma unroll
            for (int c = 0; c < 6; c++) h[c] = fmaf(v[c], cen[c] * rs, v[6 + c]);
        }

        // output: h @ w_out^T + b_out
#pragma unroll
        for (int j = 0; j < 3; j++) {
            float acc = bo[j];
#pragma unroll
            for (int k = 0; k < 6; k++) acc = fmaf(wo[j * 6 + k], h[k], acc);
            out[3 * i + j] = acc;
        }
    }
}

extern "C" void kernel_launch(void* const* d_in, const int* in_sizes, int n_in,
                              void* d_out, int out_size) {
    const float* xy    = (const float*)d_in[0];
    const float* gamma = (const float*)d_in[1];
    const float* beta  = (const float*)d_in[2];
    const float* w_in  = (const float*)d_in[3];
    const float* b_in  = (const float*)d_in[4];
    const float* w_h   = (const float*)d_in[5];
    const float* b_h   = (const float*)d_in[6];
    const float* w_out = (const float*)d_in[7];
    const float* b_out = (const float*)d_in[8];
    const float* ln_w  = (const float*)d_in[9];
    const float* ln_b  = (const float*)d_in[10];
    float* out = (float*)d_out;

    int n = in_sizes[0] / 2;

    prep_kernel<<<(NCELL * 12 + 255) / 256, 256>>>(gamma, beta, ln_w, ln_b);
    camfield_kernel<<<2048, 128>>>((const float2*)xy, w_in, b_in, w_h, b_h,
                                   w_out, b_out, out, n);
}

// round 2
// speedup vs baseline: 1.5196x; 1.5196x over previous
#include <cuda_runtime.h>
#include <cuda_fp16.h>

#define GR 16
#define NCELL 256
typedef unsigned long long ull;

// fp16 grid table: per cell 12 half2 words:
//  [0..2]  A0 pairs (gamma*ln_w - 1, layer 0, ch pairs 01/23/45)
//  [3..5]  B0 pairs (beta + gamma*ln_b, layer 0)
//  [6..8]  A1 pairs (layer 1)
//  [9..11] B1 pairs (layer 1)
__device__ unsigned g_gridh[NCELL * 12];
__constant__ float c_wts[81];   // w_in@0(12) b_in@12(6) w_h@18(36) b_h@54(6) w_out@60(18) b_out@78(3)

// ---------------- prep: fold LN affine into grids, delta-code gamma, quantize fp16 ----------------
__global__ void prep_kernel(const float* __restrict__ gamma, const float* __restrict__ beta,
                            const float* __restrict__ lnw, const float* __restrict__ lnb) {
    int idx = blockIdx.x * blockDim.x + threadIdx.x;
    if (idx >= NCELL * 12) return;
    int cell = idx / 12, j = idx - cell * 12;
    int l = j / 6, jj = j - l * 6;
    int isB = jj / 3, pr = jj - isB * 3;
    float v[2];
#pragma unroll
    for (int u = 0; u < 2; u++) {
        int c = 2 * pr + u;
        float g = gamma[(l * 6 + c) * NCELL + cell];
        if (isB) v[u] = beta[(l * 6 + c) * NCELL + cell] + g * lnb[l * 6 + c];
        else     v[u] = g * lnw[l * 6 + c] - 1.0f;
    }
    __half2 h = __floats2half2_rn(v[0], v[1]);
    g_gridh[cell * 12 + j] = *reinterpret_cast<unsigned*>(&h);
}

// ---------------- packed f32x2 helpers ----------------
__device__ __forceinline__ ull pk2(float a, float b) {
    ull r; asm("mov.b64 %0, {%1,%2};" : "=l"(r) : "f"(a), "f"(b)); return r;
}
__device__ __forceinline__ float2 upk(ull r) {
    float2 o; asm("mov.b64 {%0,%1}, %2;" : "=f"(o.x), "=f"(o.y) : "l"(r)); return o;
}
#define C2(v) pk2((v), (v))
#define FMA2(d, a, b, c) asm("fma.rn.f32x2 %0,%1,%2,%3;" : "=l"(d) : "l"(a), "l"(b), "l"(c))
#define MUL2(d, a, b)    asm("mul.rn.f32x2 %0,%1,%2;"    : "=l"(d) : "l"(a), "l"(b))
#define ADD2(d, a, b)    asm("add.rn.f32x2 %0,%1,%2;"    : "=l"(d) : "l"(a), "l"(b))

// Packed silu: zero MUFU. t = 2^(-|x|*log2e) via magic-round + deg-5 poly,
// s = t/(1+t) via seeded Newton rcp (d in [1,2]), reflect for x>0.
__device__ __forceinline__ float2 silu2(float xa, float xb) {
    ull x = pk2(xa, xb);
    ull nax = x | 0x8000000080000000ull;      // -|x|
    ull y;  MUL2(y, nax, C2(1.4426950408889634f));
    ull fm; ADD2(fm, y, C2(12582912.0f));
    float2 fmv = upk(fm);
    int n0 = __float_as_int(fmv.x) << 23;
    int n1 = __float_as_int(fmv.y) << 23;
    ull fms; ADD2(fms, fm, C2(-12582912.0f)); // round(y)
    ull f;   FMA2(f, fms, C2(-1.0f), y);      // y - round(y) in [-0.5, 0.5]
    ull p;
    FMA2(p, f, C2(1.3333558e-3f), C2(9.6181291e-3f));
    FMA2(p, f, p, C2(5.5504109e-2f));
    FMA2(p, f, p, C2(2.4022651e-1f));
    FMA2(p, f, p, C2(6.9314718e-1f));
    FMA2(p, f, p, C2(1.0f));
    float2 pv = upk(p);
    float t0 = __int_as_float(__float_as_int(pv.x) + n0);
    float t1 = __int_as_float(__float_as_int(pv.y) + n1);
    ull t = pk2(t0, t1);
    ull d;  ADD2(d, t, C2(1.0f));             // d in [1,2]
    ull r;  FMA2(r, d, C2(-8.0f / 17.0f), C2(24.0f / 17.0f));
    ull nd = d ^ 0x8000000080000000ull;
    ull u;
    FMA2(u, nd, r, C2(2.0f)); MUL2(r, r, u);
    FMA2(u, nd, r, C2(2.0f)); MUL2(r, r, u);  // rel err ~1.2e-5
    ull s;  MUL2(s, t, r);                    // sigmoid(-|x|)
    ull m;  MUL2(m, x, s);
    float2 mv = upk(m);
    float2 res;
    res.x = xa > 0.0f ? xa - mv.x : mv.x;
    res.y = xb > 0.0f ? xb - mv.y : mv.y;
    return res;
}

__device__ __forceinline__ __half2 hr(unsigned u) { return *reinterpret_cast<__half2*>(&u); }

// layernorm + FiLM (A is delta-coded: h = (1+A)*norm + B)
__device__ __forceinline__ void modulate(float* h, float2 A01, float2 A23, float2 A45,
                                         float2 B01, float2 B23, float2 B45) {
    float mu = (((h[0] + h[1]) + (h[2] + h[3])) + (h[4] + h[5])) * (1.0f / 6.0f);
    float c0 = h[0] - mu, c1 = h[1] - mu, c2 = h[2] - mu;
    float c3 = h[3] - mu, c4 = h[4] - mu, c5 = h[5] - mu;
    float ss = c0 * c0;
    ss = fmaf(c1, c1, ss); ss = fmaf(c2, c2, ss);
    ss = fmaf(c3, c3, ss); ss = fmaf(c4, c4, ss); ss = fmaf(c5, c5, ss);
    float v = fmaf(ss, 1.0f / 6.0f, 1e-5f);
    float r = __int_as_float(0x5f3759df - (__float_as_int(v) >> 1));
    float hv = 0.5f * v;
    r = r * fmaf(-hv, r * r, 1.5f);
    r = r * fmaf(-hv, r * r, 1.5f);           // rel err ~5e-6
    float t0 = c0 * r, t1 = c1 * r, t2 = c2 * r;
    float t3 = c3 * r, t4 = c4 * r, t5 = c5 * r;
    h[0] = fmaf(A01.x, t0, t0 + B01.x);
    h[1] = fmaf(A01.y, t1, t1 + B01.y);
    h[2] = fmaf(A23.x, t2, t2 + B23.x);
    h[3] = fmaf(A23.y, t3, t3 + B23.y);
    h[4] = fmaf(A45.x, t4, t4 + B45.x);
    h[5] = fmaf(A45.y, t5, t5 + B45.y);
}

#define CMB(dst, Aw, Bw, Cw, Dw) \
    dst = __hfma2(hr(Dw), W11, __hfma2(hr(Cw), W10, __hfma2(hr(Bw), W01, __hmul2(hr(Aw), W00))))

// ---------------- main kernel ----------------
__global__ __launch_bounds__(256, 2)
void camfield_kernel(const float2* __restrict__ xy, float* __restrict__ out, int n) {
    // cell stride 20 words (80B = 5x16B chunks, coprime with 8 columns)
    __shared__ __align__(16) unsigned sg[NCELL * 20];
    for (int i = threadIdx.x; i < NCELL * 12; i += blockDim.x)
        sg[(i / 12) * 20 + (i % 12)] = g_gridh[i];
    __syncthreads();

    const int stride = gridDim.x * blockDim.x;
#pragma unroll 1
    for (int i = blockIdx.x * blockDim.x + threadIdx.x; i < n; i += stride) {
        float2 pt = xy[i];

        float fx = fminf(fmaxf(fmaf(pt.x, 7.5f, 7.5f), 0.0f), 15.0f);
        float fy = fminf(fmaxf(fmaf(pt.y, 7.5f, 7.5f), 0.0f), 15.0f);
        float x0f = floorf(fx), y0f = floorf(fy);
        float wx = fx - x0f, wy = fy - y0f;
        int x0 = (int)x0f, y0 = (int)y0f;
        int x1 = min(x0 + 1, GR - 1), y1 = min(y0 + 1, GR - 1);
        const uint4* p00 = (const uint4*)&sg[((y0 << 4) + x0) * 20];
        const uint4* p01 = (const uint4*)&sg[((y0 << 4) + x1) * 20];
        const uint4* p10 = (const uint4*)&sg[((y1 << 4) + x0) * 20];
        const uint4* p11 = (const uint4*)&sg[((y1 << 4) + x1) * 20];

        float w11f = wx * wy;
        __half2 W11 = __float2half2_rn(w11f);
        __half2 W01 = __float2half2_rn(wx - w11f);
        __half2 W10 = __float2half2_rn(wy - w11f);
        __half2 W00 = __float2half2_rn(1.0f - wx - wy + w11f);

        uint4 a0 = p00[0], a1 = p00[1], a2 = p00[2];
        uint4 b0 = p01[0], b1 = p01[1], b2 = p01[2];
        uint4 c0 = p10[0], c1 = p10[1], c2 = p10[2];
        uint4 d0 = p11[0], d1 = p11[1], d2 = p11[2];

        __half2 v0, v1, v2, v3, v4, v5, v6, v7, v8, v9, v10, v11;
        CMB(v0,  a0.x, b0.x, c0.x, d0.x);  CMB(v1,  a0.y, b0.y, c0.y, d0.y);
        CMB(v2,  a0.z, b0.z, c0.z, d0.z);  CMB(v3,  a0.w, b0.w, c0.w, d0.w);
        CMB(v4,  a1.x, b1.x, c1.x, d1.x);  CMB(v5,  a1.y, b1.y, c1.y, d1.y);
        CMB(v6,  a1.z, b1.z, c1.z, d1.z);  CMB(v7,  a1.w, b1.w, c1.w, d1.w);
        CMB(v8,  a2.x, b2.x, c2.x, d2.x);  CMB(v9,  a2.y, b2.y, c2.y, d2.y);
        CMB(v10, a2.z, b2.z, c2.z, d2.z);  CMB(v11, a2.w, b2.w, c2.w, d2.w);

        // input layer: silu(xy @ w_in^T + b_in)
        float h[6];
        {
            float pre[6];
#pragma unroll
            for (int c = 0; c < 6; c++)
                pre[c] = fmaf(c_wts[2 * c], pt.x, fmaf(c_wts[2 * c + 1], pt.y, c_wts[12 + c]));
            float2 s;
            s = silu2(pre[0], pre[1]); h[0] = s.x; h[1] = s.y;
            s = silu2(pre[2], pre[3]); h[2] = s.x; h[3] = s.y;
            s = silu2(pre[4], pre[5]); h[4] = s.x; h[5] = s.y;
        }

        // layer 0 modulation
        modulate(h, __half22float2(v0), __half22float2(v1), __half22float2(v2),
                    __half22float2(v3), __half22float2(v4), __half22float2(v5));

        // hidden layer
        {
            float pre[6];
#pragma unroll
            for (int c = 0; c < 6; c++) {
                float acc = c_wts[54 + c];
#pragma unroll
                for (int k = 0; k < 6; k++) acc = fmaf(c_wts[18 + c * 6 + k], h[k], acc);
                pre[c] = acc;
            }
            float2 s;
            s = silu2(pre[0], pre[1]); h[0] = s.x; h[1] = s.y;
            s = silu2(pre[2], pre[3]); h[2] = s.x; h[3] = s.y;
            s = silu2(pre[4], pre[5]); h[4] = s.x; h[5] = s.y;
        }

        // layer 1 modulation
        modulate(h, __half22float2(v6), __half22float2(v7), __half22float2(v8),
                    __half22float2(v9), __half22float2(v10), __half22float2(v11));

        // output layer
#pragma unroll
        for (int j = 0; j < 3; j++) {
            float acc = c_wts[78 + j];
#pragma unroll
            for (int k = 0; k < 6; k++) acc = fmaf(c_wts[60 + j * 6 + k], h[k], acc);
            out[3 * i + j] = acc;
        }
    }
}

extern "C" void kernel_launch(void* const* d_in, const int* in_sizes, int n_in,
                              void* d_out, int out_size) {
    const float* xy    = (const float*)d_in[0];
    const float* gamma = (const float*)d_in[1];
    const float* beta  = (const float*)d_in[2];
    const float* w_in  = (const float*)d_in[3];
    const float* b_in  = (const float*)d_in[4];
    const float* w_h   = (const float*)d_in[5];
    const float* b_h   = (const float*)d_in[6];
    const float* w_out = (const float*)d_in[7];
    const float* b_out = (const float*)d_in[8];
    const float* ln_w  = (const float*)d_in[9];
    const float* ln_b  = (const float*)d_in[10];
    float* out = (float*)d_out;
    int n = in_sizes[0] / 2;

    cudaMemcpyToSymbolAsync(c_wts, w_in,  12 * sizeof(float),  0 * sizeof(float), cudaMemcpyDeviceToDevice);
    cudaMemcpyToSymbolAsync(c_wts, b_in,   6 * sizeof(float), 12 * sizeof(float), cudaMemcpyDeviceToDevice);
    cudaMemcpyToSymbolAsync(c_wts, w_h,   36 * sizeof(float), 18 * sizeof(float), cudaMemcpyDeviceToDevice);
    cudaMemcpyToSymbolAsync(c_wts, b_h,    6 * sizeof(float), 54 * sizeof(float), cudaMemcpyDeviceToDevice);
    cudaMemcpyToSymbolAsync(c_wts, w_out, 18 * sizeof(float), 60 * sizeof(float), cudaMemcpyDeviceToDevice);
    cudaMemcpyToSymbolAsync(c_wts, b_out,  3 * sizeof(float), 78 * sizeof(float), cudaMemcpyDeviceToDevice);

    prep_kernel<<<(NCELL * 12 + 255) / 256, 256>>>(gamma, beta, ln_w, ln_b);
    camfield_kernel<<<1184, 256>>>((const float2*)xy, out, n);
}